// round 6
// baseline (speedup 1.0000x reference)
#include <cuda_runtime.h>
#include <cstdint>

// Quantize x to nearest codeword on grid {i - 7.5 : i=0..15}.
// Matches jnp.argmax(2*x*g - g^2) tie-breaking (first/lowest index on exact
// midpoint ties) via idx = clamp(ceil(x+8)-1, 0, 15).
__device__ __forceinline__ int quant_idx(float x) {
    int k = __float2int_ru(x + 8.0f) - 1;   // ceil(x+8) - 1
    k = max(0, min(15, k));
    return k;
}

#ifndef VPT
#define VPT 4   // float4 vectors per thread
#endif

// Float-promoted output layout: [N x float32 vals][N x float32 idx]
// Each thread handles VPT grid-strided float4s; all loads issued up-front
// (MLP_p1 = VPT) with streaming cache hints (touch-once data).
__global__ void __launch_bounds__(256)
quant_float_v4(const float4* __restrict__ x4,
               float4* __restrict__ v4,
               float4* __restrict__ idxf4,
               int n4)
{
    const int stride = gridDim.x * blockDim.x;
    const int base = blockIdx.x * blockDim.x + threadIdx.x;

    float4 x[VPT];
    int idx[VPT];

    // Front-batched loads for memory-level parallelism.
    #pragma unroll
    for (int j = 0; j < VPT; j++) {
        int i = base + j * stride;
        idx[j] = i;
        if (i < n4) x[j] = __ldcs(&x4[i]);
    }

    #pragma unroll
    for (int j = 0; j < VPT; j++) {
        int i = idx[j];
        if (i < n4) {
            float f0 = (float)quant_idx(x[j].x);
            float f1 = (float)quant_idx(x[j].y);
            float f2 = (float)quant_idx(x[j].z);
            float f3 = (float)quant_idx(x[j].w);
            __stcs(&v4[i],    make_float4(f0 - 7.5f, f1 - 7.5f,
                                          f2 - 7.5f, f3 - 7.5f));
            __stcs(&idxf4[i], make_float4(f0, f1, f2, f3));
        }
    }
}

// Byte-concatenated output layout: [N x float32 vals][N x uint8 idx]
__global__ void __launch_bounds__(256)
quant_bytes_v4(const float4* __restrict__ x4,
               float4* __restrict__ v4,
               uchar4* __restrict__ i4,
               int n4)
{
    const int stride = gridDim.x * blockDim.x;
    const int base = blockIdx.x * blockDim.x + threadIdx.x;

    float4 x[VPT];
    int idx[VPT];

    #pragma unroll
    for (int j = 0; j < VPT; j++) {
        int i = base + j * stride;
        idx[j] = i;
        if (i < n4) x[j] = __ldcs(&x4[i]);
    }

    #pragma unroll
    for (int j = 0; j < VPT; j++) {
        int i = idx[j];
        if (i < n4) {
            int k0 = quant_idx(x[j].x);
            int k1 = quant_idx(x[j].y);
            int k2 = quant_idx(x[j].z);
            int k3 = quant_idx(x[j].w);
            __stcs(&v4[i], make_float4((float)k0 - 7.5f, (float)k1 - 7.5f,
                                       (float)k2 - 7.5f, (float)k3 - 7.5f));
            i4[i] = make_uchar4((unsigned char)k0, (unsigned char)k1,
                                (unsigned char)k2, (unsigned char)k3);
        }
    }
}

// Scalar tails (N = 2^23 here so they never fire, but stay generic).
__global__ void quant_tail_float_kernel(const float* __restrict__ x,
                                        float* __restrict__ vals,
                                        float* __restrict__ idxf,
                                        int start, int n)
{
    int i = start + blockIdx.x * blockDim.x + threadIdx.x;
    if (i >= n) return;
    int k = quant_idx(x[i]);
    vals[i] = (float)k - 7.5f;
    idxf[i] = (float)k;
}

__global__ void quant_tail_kernel(const float* __restrict__ x,
                                  float* __restrict__ vals,
                                  unsigned char* __restrict__ idx,
                                  int start, int n)
{
    int i = start + blockIdx.x * blockDim.x + threadIdx.x;
    if (i >= n) return;
    int k = quant_idx(x[i]);
    vals[i] = (float)k - 7.5f;
    idx[i]  = (unsigned char)k;
}

extern "C" void kernel_launch(void* const* d_in, const int* in_sizes, int n_in,
                              void* d_out, int out_size)
{
    const float* X = (const float*)d_in[0];   // (N,1) float32
    const int N = in_sizes[0];

    const int n4 = N / 4;
    const int tail = N - n4 * 4;
    const int threads = 256;
    const int elems_per_block = threads * VPT;
    const int blocks = (n4 + elems_per_block - 1) / elems_per_block;

    float* vals = (float*)d_out;

    if ((long long)out_size == 2LL * (long long)N) {
        // [vals (N fp32) | idx promoted to fp32 (N)]
        float* idxf = vals + N;
        if (n4 > 0)
            quant_float_v4<<<blocks, threads>>>(
                (const float4*)X, (float4*)vals, (float4*)idxf, n4);
        if (tail > 0)
            quant_tail_float_kernel<<<1, 32>>>(X, vals, idxf, n4 * 4, N);
    } else {
        // [vals (N fp32) | idx (N uint8)]
        unsigned char* idx = (unsigned char*)d_out + (size_t)N * 4;
        if (n4 > 0)
            quant_bytes_v4<<<blocks, threads>>>(
                (const float4*)X, (float4*)vals, (uchar4*)idx, n4);
        if (tail > 0)
            quant_tail_kernel<<<1, 32>>>(X, vals, idx, n4 * 4, N);
    }
}

// round 9
// speedup vs baseline: 1.0152x; 1.0152x over previous
#include <cuda_runtime.h>
#include <cstdint>

// Quantize x to nearest codeword on grid {i - 7.5 : i=0..15}.
// Matches jnp.argmax(2*x*g - g^2) tie-breaking (first/lowest index on exact
// midpoint ties) via idx = clamp(ceil(x+8)-1, 0, 15).
__device__ __forceinline__ int quant_idx(float x) {
    int k = __float2int_ru(x + 8.0f) - 1;   // ceil(x+8) - 1
    k = max(0, min(15, k));
    return k;
}

#ifndef VPT
#define VPT 4   // float4 vectors per thread
#endif

// Float-promoted output layout: [N x float32 vals][N x float32 idx]
// Each thread handles VPT grid-strided float4s; all loads issued up-front
// (MLP_p1 = VPT) with streaming cache hints (touch-once data).
__global__ void __launch_bounds__(256)
quant_float_v4(const float4* __restrict__ x4,
               float4* __restrict__ v4,
               float4* __restrict__ idxf4,
               int n4)
{
    const int stride = gridDim.x * blockDim.x;
    const int base = blockIdx.x * blockDim.x + threadIdx.x;

    float4 x[VPT];
    int idx[VPT];

    // Front-batched loads for memory-level parallelism.
    #pragma unroll
    for (int j = 0; j < VPT; j++) {
        int i = base + j * stride;
        idx[j] = i;
        if (i < n4) x[j] = __ldcs(&x4[i]);
    }

    #pragma unroll
    for (int j = 0; j < VPT; j++) {
        int i = idx[j];
        if (i < n4) {
            float f0 = (float)quant_idx(x[j].x);
            float f1 = (float)quant_idx(x[j].y);
            float f2 = (float)quant_idx(x[j].z);
            float f3 = (float)quant_idx(x[j].w);
            __stcs(&v4[i],    make_float4(f0 - 7.5f, f1 - 7.5f,
                                          f2 - 7.5f, f3 - 7.5f));
            __stcs(&idxf4[i], make_float4(f0, f1, f2, f3));
        }
    }
}

// Byte-concatenated output layout: [N x float32 vals][N x uint8 idx]
__global__ void __launch_bounds__(256)
quant_bytes_v4(const float4* __restrict__ x4,
               float4* __restrict__ v4,
               uchar4* __restrict__ i4,
               int n4)
{
    const int stride = gridDim.x * blockDim.x;
    const int base = blockIdx.x * blockDim.x + threadIdx.x;

    float4 x[VPT];
    int idx[VPT];

    #pragma unroll
    for (int j = 0; j < VPT; j++) {
        int i = base + j * stride;
        idx[j] = i;
        if (i < n4) x[j] = __ldcs(&x4[i]);
    }

    #pragma unroll
    for (int j = 0; j < VPT; j++) {
        int i = idx[j];
        if (i < n4) {
            int k0 = quant_idx(x[j].x);
            int k1 = quant_idx(x[j].y);
            int k2 = quant_idx(x[j].z);
            int k3 = quant_idx(x[j].w);
            __stcs(&v4[i], make_float4((float)k0 - 7.5f, (float)k1 - 7.5f,
                                       (float)k2 - 7.5f, (float)k3 - 7.5f));
            i4[i] = make_uchar4((unsigned char)k0, (unsigned char)k1,
                                (unsigned char)k2, (unsigned char)k3);
        }
    }
}

// Scalar tails (N = 2^23 here so they never fire, but stay generic).
__global__ void quant_tail_float_kernel(const float* __restrict__ x,
                                        float* __restrict__ vals,
                                        float* __restrict__ idxf,
                                        int start, int n)
{
    int i = start + blockIdx.x * blockDim.x + threadIdx.x;
    if (i >= n) return;
    int k = quant_idx(x[i]);
    vals[i] = (float)k - 7.5f;
    idxf[i] = (float)k;
}

__global__ void quant_tail_kernel(const float* __restrict__ x,
                                  float* __restrict__ vals,
                                  unsigned char* __restrict__ idx,
                                  int start, int n)
{
    int i = start + blockIdx.x * blockDim.x + threadIdx.x;
    if (i >= n) return;
    int k = quant_idx(x[i]);
    vals[i] = (float)k - 7.5f;
    idx[i]  = (unsigned char)k;
}

extern "C" void kernel_launch(void* const* d_in, const int* in_sizes, int n_in,
                              void* d_out, int out_size)
{
    const float* X = (const float*)d_in[0];   // (N,1) float32
    const int N = in_sizes[0];

    const int n4 = N / 4;
    const int tail = N - n4 * 4;
    const int threads = 256;
    const int elems_per_block = threads * VPT;
    const int blocks = (n4 + elems_per_block - 1) / elems_per_block;

    float* vals = (float*)d_out;

    if ((long long)out_size == 2LL * (long long)N) {
        // [vals (N fp32) | idx promoted to fp32 (N)]
        float* idxf = vals + N;
        if (n4 > 0)
            quant_float_v4<<<blocks, threads>>>(
                (const float4*)X, (float4*)vals, (float4*)idxf, n4);
        if (tail > 0)
            quant_tail_float_kernel<<<1, 32>>>(X, vals, idxf, n4 * 4, N);
    } else {
        // [vals (N fp32) | idx (N uint8)]
        unsigned char* idx = (unsigned char*)d_out + (size_t)N * 4;
        if (n4 > 0)
            quant_bytes_v4<<<blocks, threads>>>(
                (const float4*)X, (float4*)vals, (uchar4*)idx, n4);
        if (tail > 0)
            quant_tail_kernel<<<1, 32>>>(X, vals, idx, n4 * 4, N);
    }
}